// round 1
// baseline (speedup 1.0000x reference)
#include <cuda_runtime.h>
#include <cuda_bf16.h>

#define N_SRC  100000
#define N_DST  50000
#define E_CNT  600000
#define D      128          // D_IN == D_OUT == 128

// ---------------- device scratch (no allocation allowed) ----------------
__device__ float g_WH[(size_t)N_SRC * D];   // 51.2 MB, fits in L2 for agg phase
__device__ int   g_deg[N_DST];
__device__ int   g_cursor[N_DST];
__device__ int   g_off[N_DST + 1];
__device__ int   g_edges[E_CNT];            // src id per CSR slot

// ---------------- init: zero counters ----------------
__global__ void zero_counts_kernel() {
    int i = blockIdx.x * blockDim.x + threadIdx.x;
    if (i < N_DST) { g_deg[i] = 0; g_cursor[i] = 0; }
}

// ---------------- GEMM: WH = H_src @ W + b ----------------
// block: 256 threads = (tx 0..31 -> 4 cols each, ty 0..7 -> 8 rows each)
// tile: 64 rows x 128 cols per block
__global__ __launch_bounds__(256) void gemm_kernel(const float* __restrict__ H,
                                                   const float* __restrict__ W,
                                                   const float* __restrict__ b) {
    __shared__ float sH[64][D];             // 32 KB
    const int block_row = blockIdx.x * 64;
    const int tid = threadIdx.x;

    // load H tile (64x128 floats = 2048 float4, 8 per thread), guard tail rows
    const float4* H4 = (const float4*)H;
    for (int i = tid; i < 64 * 32; i += 256) {
        int r = i >> 5, c = i & 31;
        int gr = block_row + r;
        float4 v = make_float4(0.f, 0.f, 0.f, 0.f);
        if (gr < N_SRC) v = H4[(size_t)gr * 32 + c];
        *(float4*)&sH[r][c * 4] = v;
    }
    __syncthreads();

    const int tx = tid & 31, ty = tid >> 5;
    const int col  = tx * 4;
    const int row0 = ty * 8;

    float4 bias = *(const float4*)&b[col];
    float4 acc[8];
#pragma unroll
    for (int r = 0; r < 8; r++) acc[r] = bias;

    const float4* W4 = (const float4*)W;
#pragma unroll 4
    for (int k = 0; k < D; k += 4) {
        float4 w0 = W4[(size_t)(k + 0) * 32 + tx];
        float4 w1 = W4[(size_t)(k + 1) * 32 + tx];
        float4 w2 = W4[(size_t)(k + 2) * 32 + tx];
        float4 w3 = W4[(size_t)(k + 3) * 32 + tx];
#pragma unroll
        for (int r = 0; r < 8; r++) {
            float4 h = *(const float4*)&sH[row0 + r][k];   // broadcast LDS.128
            acc[r].x += h.x * w0.x + h.y * w1.x + h.z * w2.x + h.w * w3.x;
            acc[r].y += h.x * w0.y + h.y * w1.y + h.z * w2.y + h.w * w3.y;
            acc[r].z += h.x * w0.z + h.y * w1.z + h.z * w2.z + h.w * w3.z;
            acc[r].w += h.x * w0.w + h.y * w1.w + h.z * w2.w + h.w * w3.w;
        }
    }

#pragma unroll
    for (int r = 0; r < 8; r++) {
        int gr = block_row + row0 + r;
        if (gr < N_SRC)
            *(float4*)&g_WH[(size_t)gr * D + col] = acc[r];
    }
}

// ---------------- degree counting ----------------
__global__ void count_kernel(const int* __restrict__ edge_dst) {
    int e = blockIdx.x * blockDim.x + threadIdx.x;
    if (e < E_CNT) atomicAdd(&g_deg[edge_dst[e]], 1);
}

// ---------------- single-block exclusive scan over g_deg -> g_off ----------------
__global__ __launch_bounds__(1024) void scan_kernel() {
    __shared__ int partial[1024];
    const int tid = threadIdx.x;
    const int chunk = (N_DST + 1023) / 1024;   // 49
    const int start = tid * chunk;
    const int end   = min(start + chunk, N_DST);

    int s = 0;
    for (int i = start; i < end; i++) s += g_deg[i];
    partial[tid] = s;
    __syncthreads();

    // Hillis-Steele inclusive scan
    for (int off = 1; off < 1024; off <<= 1) {
        int v = 0;
        if (tid >= off) v = partial[tid - off];
        __syncthreads();
        partial[tid] += v;
        __syncthreads();
    }

    int run = (tid > 0) ? partial[tid - 1] : 0;   // exclusive prefix of this chunk
    for (int i = start; i < end; i++) {
        g_off[i] = run;
        run += g_deg[i];
    }
    if (tid == 1023) g_off[N_DST] = partial[1023];  // == E_CNT
}

// ---------------- CSR fill ----------------
__global__ void fill_kernel(const int* __restrict__ edge_src,
                            const int* __restrict__ edge_dst) {
    int e = blockIdx.x * blockDim.x + threadIdx.x;
    if (e < E_CNT) {
        int d = edge_dst[e];
        int pos = g_off[d] + atomicAdd(&g_cursor[d], 1);
        g_edges[pos] = edge_src[e];
    }
}

// ---------------- aggregation: one warp per dst, no atomics ----------------
__global__ __launch_bounds__(256) void agg_kernel(float* __restrict__ out) {
    int warp = (blockIdx.x * blockDim.x + threadIdx.x) >> 5;
    int lane = threadIdx.x & 31;
    if (warp >= N_DST) return;

    int s0 = g_off[warp];
    int s1 = g_off[warp + 1];

    const float4* WH4 = (const float4*)g_WH;
    float4 acc = make_float4(0.f, 0.f, 0.f, 0.f);

    int i = s0;
    // unroll by 2 for MLP
    for (; i + 1 < s1; i += 2) {
        int srcA = g_edges[i];
        int srcB = g_edges[i + 1];
        float4 a = WH4[(size_t)srcA * 32 + lane];
        float4 c = WH4[(size_t)srcB * 32 + lane];
        acc.x += a.x + c.x; acc.y += a.y + c.y;
        acc.z += a.z + c.z; acc.w += a.w + c.w;
    }
    if (i < s1) {
        int src = g_edges[i];
        float4 a = WH4[(size_t)src * 32 + lane];
        acc.x += a.x; acc.y += a.y; acc.z += a.z; acc.w += a.w;
    }

    float inv = 1.0f / fmaxf((float)(s1 - s0), 1.0f);
    acc.x = fmaxf(acc.x * inv, 0.f);
    acc.y = fmaxf(acc.y * inv, 0.f);
    acc.z = fmaxf(acc.z * inv, 0.f);
    acc.w = fmaxf(acc.w * inv, 0.f);

    ((float4*)out)[(size_t)warp * 32 + lane] = acc;
}

// ---------------- launch ----------------
extern "C" void kernel_launch(void* const* d_in, const int* in_sizes, int n_in,
                              void* d_out, int out_size) {
    const float* H_src    = (const float*)d_in[0];
    const float* W        = (const float*)d_in[1];
    const float* b        = (const float*)d_in[2];
    const int*   edge_src = (const int*)d_in[3];
    const int*   edge_dst = (const int*)d_in[4];
    float* out = (float*)d_out;

    zero_counts_kernel<<<(N_DST + 255) / 256, 256>>>();
    gemm_kernel<<<(N_SRC + 63) / 64, 256>>>(H_src, W, b);
    count_kernel<<<(E_CNT + 255) / 256, 256>>>(edge_dst);
    scan_kernel<<<1, 1024>>>();
    fill_kernel<<<(E_CNT + 255) / 256, 256>>>(edge_src, edge_dst);
    agg_kernel<<<(N_DST * 32 + 255) / 256, 256>>>(out);
}

// round 2
// speedup vs baseline: 1.2736x; 1.2736x over previous
#include <cuda_runtime.h>
#include <cuda_bf16.h>

#define N_SRC  100000
#define N_DST  50000
#define E_CNT  600000
#define D      128          // D_IN == D_OUT == 128

#define SCAN_CHUNK 512
#define SCAN_NB    ((N_DST + SCAN_CHUNK - 1) / SCAN_CHUNK)   // 98

// ---------------- device scratch (no allocation allowed) ----------------
__device__ float g_WH[(size_t)N_SRC * D];   // 51.2 MB, mostly L2-resident for agg
__device__ int   g_deg[N_DST];
__device__ int   g_cursor[N_DST];
__device__ int   g_off[N_DST + 1];
__device__ int   g_edges[E_CNT];            // src id per CSR slot
__device__ int   g_part[SCAN_NB];           // per-block partial sums

// ---------------- init: zero counters ----------------
__global__ void zero_counts_kernel() {
    int i = blockIdx.x * blockDim.x + threadIdx.x;
    if (i < N_DST) { g_deg[i] = 0; g_cursor[i] = 0; }
}

// ---------------- GEMM: WH = H_src @ W + b ----------------
// block: 256 threads = (tx 0..31 -> 4 cols each, ty 0..7 -> 8 rows each)
// tile: 64 rows x 128 cols per block
__global__ __launch_bounds__(256) void gemm_kernel(const float* __restrict__ H,
                                                   const float* __restrict__ W,
                                                   const float* __restrict__ b) {
    __shared__ float sH[64][D];             // 32 KB
    const int block_row = blockIdx.x * 64;
    const int tid = threadIdx.x;

    const float4* H4 = (const float4*)H;
    for (int i = tid; i < 64 * 32; i += 256) {
        int r = i >> 5, c = i & 31;
        int gr = block_row + r;
        float4 v = make_float4(0.f, 0.f, 0.f, 0.f);
        if (gr < N_SRC) v = H4[(size_t)gr * 32 + c];
        *(float4*)&sH[r][c * 4] = v;
    }
    __syncthreads();

    const int tx = tid & 31, ty = tid >> 5;
    const int col  = tx * 4;
    const int row0 = ty * 8;

    float4 bias = *(const float4*)&b[col];
    float4 acc[8];
#pragma unroll
    for (int r = 0; r < 8; r++) acc[r] = bias;

    const float4* W4 = (const float4*)W;
#pragma unroll 4
    for (int k = 0; k < D; k += 4) {
        float4 w0 = W4[(size_t)(k + 0) * 32 + tx];
        float4 w1 = W4[(size_t)(k + 1) * 32 + tx];
        float4 w2 = W4[(size_t)(k + 2) * 32 + tx];
        float4 w3 = W4[(size_t)(k + 3) * 32 + tx];
#pragma unroll
        for (int r = 0; r < 8; r++) {
            float4 h = *(const float4*)&sH[row0 + r][k];   // broadcast LDS.128
            acc[r].x += h.x * w0.x + h.y * w1.x + h.z * w2.x + h.w * w3.x;
            acc[r].y += h.x * w0.y + h.y * w1.y + h.z * w2.y + h.w * w3.y;
            acc[r].z += h.x * w0.z + h.y * w1.z + h.z * w2.z + h.w * w3.z;
            acc[r].w += h.x * w0.w + h.y * w1.w + h.z * w2.w + h.w * w3.w;
        }
    }

#pragma unroll
    for (int r = 0; r < 8; r++) {
        int gr = block_row + row0 + r;
        if (gr < N_SRC)
            *(float4*)&g_WH[(size_t)gr * D + col] = acc[r];
    }
}

// ---------------- degree counting ----------------
__global__ void count_kernel(const int* __restrict__ edge_dst) {
    int e = blockIdx.x * blockDim.x + threadIdx.x;
    if (e < E_CNT) atomicAdd(&g_deg[edge_dst[e]], 1);
}

// ---------------- 3-phase hierarchical scan ----------------
// Phase A: per-block sums of g_deg chunks
__global__ __launch_bounds__(SCAN_CHUNK) void scanA_kernel() {
    __shared__ int warp_sum[SCAN_CHUNK / 32];
    int idx = blockIdx.x * SCAN_CHUNK + threadIdx.x;
    int v = (idx < N_DST) ? g_deg[idx] : 0;

    // warp reduce
    for (int o = 16; o > 0; o >>= 1) v += __shfl_down_sync(0xffffffffu, v, o);
    int wid = threadIdx.x >> 5, lid = threadIdx.x & 31;
    if (lid == 0) warp_sum[wid] = v;
    __syncthreads();
    if (wid == 0) {
        int s = (lid < SCAN_CHUNK / 32) ? warp_sum[lid] : 0;
        for (int o = 16; o > 0; o >>= 1) s += __shfl_down_sync(0xffffffffu, s, o);
        if (lid == 0) g_part[blockIdx.x] = s;
    }
}

// Phase B: single small block turns g_part into its exclusive prefix sum
__global__ __launch_bounds__(128) void scanB_kernel() {
    __shared__ int sh[128];
    int tid = threadIdx.x;
    int v = (tid < SCAN_NB) ? g_part[tid] : 0;
    sh[tid] = v;
    __syncthreads();
    // Hillis-Steele inclusive over 128
    for (int o = 1; o < 128; o <<= 1) {
        int t = (tid >= o) ? sh[tid - o] : 0;
        __syncthreads();
        sh[tid] += t;
        __syncthreads();
    }
    if (tid < SCAN_NB) g_part[tid] = sh[tid] - v;   // exclusive
}

// Phase C: per-block exclusive scan + global offset -> g_off
__global__ __launch_bounds__(SCAN_CHUNK) void scanC_kernel() {
    __shared__ int sh[SCAN_CHUNK];
    int tid = threadIdx.x;
    int idx = blockIdx.x * SCAN_CHUNK + tid;
    int v = (idx < N_DST) ? g_deg[idx] : 0;
    sh[tid] = v;
    __syncthreads();
    for (int o = 1; o < SCAN_CHUNK; o <<= 1) {
        int t = (tid >= o) ? sh[tid - o] : 0;
        __syncthreads();
        sh[tid] += t;
        __syncthreads();
    }
    int base = g_part[blockIdx.x];
    if (idx < N_DST) {
        g_off[idx] = base + sh[tid] - v;            // exclusive prefix
        if (idx == N_DST - 1) g_off[N_DST] = base + sh[tid];
    }
}

// ---------------- CSR fill ----------------
__global__ void fill_kernel(const int* __restrict__ edge_src,
                            const int* __restrict__ edge_dst) {
    int e = blockIdx.x * blockDim.x + threadIdx.x;
    if (e < E_CNT) {
        int d = edge_dst[e];
        int pos = g_off[d] + atomicAdd(&g_cursor[d], 1);
        g_edges[pos] = edge_src[e];
    }
}

// ---------------- aggregation: one warp per dst, no atomics ----------------
__global__ __launch_bounds__(256) void agg_kernel(float* __restrict__ out) {
    int warp = (blockIdx.x * blockDim.x + threadIdx.x) >> 5;
    int lane = threadIdx.x & 31;
    if (warp >= N_DST) return;

    int s0 = g_off[warp];
    int s1 = g_off[warp + 1];

    const float4* WH4 = (const float4*)g_WH;
    float4 acc = make_float4(0.f, 0.f, 0.f, 0.f);

    int i = s0;
    // unroll by 4 for MLP
    for (; i + 3 < s1; i += 4) {
        int sA = g_edges[i];
        int sB = g_edges[i + 1];
        int sC = g_edges[i + 2];
        int sD = g_edges[i + 3];
        float4 a = WH4[(size_t)sA * 32 + lane];
        float4 c = WH4[(size_t)sB * 32 + lane];
        float4 e = WH4[(size_t)sC * 32 + lane];
        float4 f = WH4[(size_t)sD * 32 + lane];
        acc.x += (a.x + c.x) + (e.x + f.x);
        acc.y += (a.y + c.y) + (e.y + f.y);
        acc.z += (a.z + c.z) + (e.z + f.z);
        acc.w += (a.w + c.w) + (e.w + f.w);
    }
    for (; i < s1; i++) {
        int src = g_edges[i];
        float4 a = WH4[(size_t)src * 32 + lane];
        acc.x += a.x; acc.y += a.y; acc.z += a.z; acc.w += a.w;
    }

    float inv = 1.0f / fmaxf((float)(s1 - s0), 1.0f);
    acc.x = fmaxf(acc.x * inv, 0.f);
    acc.y = fmaxf(acc.y * inv, 0.f);
    acc.z = fmaxf(acc.z * inv, 0.f);
    acc.w = fmaxf(acc.w * inv, 0.f);

    ((float4*)out)[(size_t)warp * 32 + lane] = acc;
}

// ---------------- launch ----------------
extern "C" void kernel_launch(void* const* d_in, const int* in_sizes, int n_in,
                              void* d_out, int out_size) {
    const float* H_src    = (const float*)d_in[0];
    const float* W        = (const float*)d_in[1];
    const float* b        = (const float*)d_in[2];
    const int*   edge_src = (const int*)d_in[3];
    const int*   edge_dst = (const int*)d_in[4];
    float* out = (float*)d_out;

    zero_counts_kernel<<<(N_DST + 255) / 256, 256>>>();
    gemm_kernel<<<(N_SRC + 63) / 64, 256>>>(H_src, W, b);
    count_kernel<<<(E_CNT + 255) / 256, 256>>>(edge_dst);
    scanA_kernel<<<SCAN_NB, SCAN_CHUNK>>>();
    scanB_kernel<<<1, 128>>>();
    scanC_kernel<<<SCAN_NB, SCAN_CHUNK>>>();
    fill_kernel<<<(E_CNT + 255) / 256, 256>>>(edge_src, edge_dst);
    agg_kernel<<<(N_DST * 32 + 255) / 256, 256>>>(out);
}

// round 4
// speedup vs baseline: 1.7513x; 1.3751x over previous
#include <cuda_runtime.h>
#include <cuda_bf16.h>
#include <cstdint>

#define N_SRC  100000
#define N_DST  50000
#define E_CNT  600000
#define D      128          // D_IN == D_OUT == 128

#define SCAN_CHUNK 512
#define SCAN_NB    ((N_DST + SCAN_CHUNK - 1) / SCAN_CHUNK)   // 98

#define TILE_M 128
#define GRID_M ((N_SRC + TILE_M - 1) / TILE_M)               // 782

// padded row stride for smem tiles (bf16 elements): 128 + 8
#define LDA 136

// ---------------- device scratch (no allocation allowed) ----------------
__device__ float g_WH[(size_t)N_SRC * D];   // 51.2 MB
__device__ int   g_deg[N_DST];
__device__ int   g_cursor[N_DST];
__device__ int   g_off[N_DST + 1];
__device__ int   g_edges[E_CNT];
__device__ int   g_part[SCAN_NB];
// W split into bf16 hi/lo, stored as B[n][k] (= W[k][n]) row-major, k contiguous
__device__ __nv_bfloat16 g_Whi[D * D];
__device__ __nv_bfloat16 g_Wlo[D * D];

// ---------------- init: zero counters ----------------
__global__ void zero_counts_kernel() {
    int i = blockIdx.x * blockDim.x + threadIdx.x;
    if (i < N_DST) { g_deg[i] = 0; g_cursor[i] = 0; }
}

// ---------------- W split: B[n][k] = W[k][n], bf16 hi/lo ----------------
__global__ __launch_bounds__(256) void wsplit_kernel(const float* __restrict__ W) {
    int e = blockIdx.x * blockDim.x + threadIdx.x;   // 0..16383
    if (e >= D * D) return;
    int n = e >> 7, k = e & 127;
    float w = W[k * D + n];
    __nv_bfloat16 hi = __float2bfloat16_rn(w);
    float lo_f = w - __bfloat162float(hi);
    g_Whi[n * D + k] = hi;
    g_Wlo[n * D + k] = __float2bfloat16_rn(lo_f);
}

// ---------------- mma.sync helper ----------------
__device__ __forceinline__ void mma16816(float* c,
                                         uint32_t a0, uint32_t a1, uint32_t a2, uint32_t a3,
                                         uint32_t b0, uint32_t b1) {
    asm volatile(
        "mma.sync.aligned.m16n8k16.row.col.f32.bf16.bf16.f32 "
        "{%0,%1,%2,%3}, {%4,%5,%6,%7}, {%8,%9}, {%0,%1,%2,%3};"
        : "+f"(c[0]), "+f"(c[1]), "+f"(c[2]), "+f"(c[3])
        : "r"(a0), "r"(a1), "r"(a2), "r"(a3), "r"(b0), "r"(b1));
}

__device__ __forceinline__ uint32_t pack2(float a, float b) {
    __nv_bfloat162 t = __floats2bfloat162_rn(a, b);
    return *(uint32_t*)&t;
}

// ---------------- tensor-core GEMM via mma.sync: WH = H @ W + b --------------
// dyn smem (bytes): bias @0 (512), A_hi @512, A_lo, B_hi, B_lo (each 128*136*2)
#define SM_BIAS  0
#define SM_AHI   512
#define SM_ALO   (SM_AHI + TILE_M * LDA * 2)
#define SM_BHI   (SM_ALO + TILE_M * LDA * 2)
#define SM_BLO   (SM_BHI + TILE_M * LDA * 2)
#define SM_TOTAL (SM_BLO + TILE_M * LDA * 2)       // 512 + 4*34816 = 139776

__global__ __launch_bounds__(256, 1) void gemm_tc_kernel(const float* __restrict__ H,
                                                         const float* __restrict__ b) {
    extern __shared__ char smem[];
    const int tid = threadIdx.x;
    const int wid = tid >> 5, lane = tid & 31;
    const int block_row = blockIdx.x * TILE_M;

    __nv_bfloat16* sAhi = (__nv_bfloat16*)(smem + SM_AHI);
    __nv_bfloat16* sAlo = (__nv_bfloat16*)(smem + SM_ALO);
    __nv_bfloat16* sBhi = (__nv_bfloat16*)(smem + SM_BHI);
    __nv_bfloat16* sBlo = (__nv_bfloat16*)(smem + SM_BLO);
    float* sbias = (float*)(smem + SM_BIAS);

    // ---- load B tiles (16B chunks, padded rows) ----
    for (int i = tid; i < D * 16; i += 256) {          // 128 rows x 16 chunks of 8 bf16
        int n = i >> 4, q = i & 15;
        *(uint4*)&sBhi[n * LDA + q * 8] = *(const uint4*)&g_Whi[n * D + q * 8];
        *(uint4*)&sBlo[n * LDA + q * 8] = *(const uint4*)&g_Wlo[n * D + q * 8];
    }
    if (tid < D) sbias[tid] = b[tid];

    // ---- load + split A tile ----
    {
        const int row = tid >> 1;
        const int k0  = (tid & 1) * 64;
        const int grow = block_row + row;
        const float4* H4 = (const float4*)H;
#pragma unroll 4
        for (int q = 0; q < 16; q++) {
            int k = k0 + q * 4;
            float4 v = make_float4(0.f, 0.f, 0.f, 0.f);
            if (grow < N_SRC) v = H4[(size_t)grow * 32 + (k >> 2)];
            __nv_bfloat16 h0 = __float2bfloat16_rn(v.x);
            __nv_bfloat16 h1 = __float2bfloat16_rn(v.y);
            __nv_bfloat16 h2 = __float2bfloat16_rn(v.z);
            __nv_bfloat16 h3 = __float2bfloat16_rn(v.w);
            uint2 hv, lv;
            { __nv_bfloat162 t0; t0.x = h0; t0.y = h1; hv.x = *(uint32_t*)&t0;
              __nv_bfloat162 t1; t1.x = h2; t1.y = h3; hv.y = *(uint32_t*)&t1; }
            lv.x = pack2(v.x - __bfloat162float(h0), v.y - __bfloat162float(h1));
            lv.y = pack2(v.z - __bfloat162float(h2), v.w - __bfloat162float(h3));
            *(uint2*)&sAhi[row * LDA + k] = hv;
            *(uint2*)&sAlo[row * LDA + k] = lv;
        }
    }
    __syncthreads();

    // ---- per-warp MMA: warp covers rows [32*wr, +32), cols [64*wc, +64) ----
    const int wr = wid & 3, wc = wid >> 2;
    const int m0 = wr * 32, n0 = wc * 64;
    const int gid = lane >> 2;            // 0..7
    const int tg  = lane & 3;             // 0..3

    float acc[2][8][4];
#pragma unroll
    for (int mt = 0; mt < 2; mt++)
#pragma unroll
        for (int nt = 0; nt < 8; nt++)
#pragma unroll
            for (int q = 0; q < 4; q++) acc[mt][nt][q] = 0.f;

#pragma unroll
    for (int pass = 0; pass < 3; pass++) {
        const __nv_bfloat16* A = (pass == 2) ? sAlo : sAhi;
        const __nv_bfloat16* B = (pass == 1) ? sBlo : sBhi;
#pragma unroll
        for (int ks = 0; ks < 8; ks++) {
            const int k0 = ks * 16;
            uint32_t af[2][4];
#pragma unroll
            for (int mt = 0; mt < 2; mt++) {
                const int r = m0 + mt * 16 + gid;
                af[mt][0] = *(const uint32_t*)&A[(r    ) * LDA + k0 + tg * 2];
                af[mt][1] = *(const uint32_t*)&A[(r + 8) * LDA + k0 + tg * 2];
                af[mt][2] = *(const uint32_t*)&A[(r    ) * LDA + k0 + 8 + tg * 2];
                af[mt][3] = *(const uint32_t*)&A[(r + 8) * LDA + k0 + 8 + tg * 2];
            }
#pragma unroll
            for (int nt = 0; nt < 8; nt++) {
                const int n = n0 + nt * 8 + gid;
                uint32_t b0 = *(const uint32_t*)&B[n * LDA + k0 + tg * 2];
                uint32_t b1 = *(const uint32_t*)&B[n * LDA + k0 + 8 + tg * 2];
                mma16816(acc[0][nt], af[0][0], af[0][1], af[0][2], af[0][3], b0, b1);
                mma16816(acc[1][nt], af[1][0], af[1][1], af[1][2], af[1][3], b0, b1);
            }
        }
    }

    // ---- epilogue: bias + store to g_WH ----
#pragma unroll
    for (int mt = 0; mt < 2; mt++) {
        const int r  = m0 + mt * 16 + gid;
        const int g0 = block_row + r;
#pragma unroll
        for (int nt = 0; nt < 8; nt++) {
            const int c = n0 + nt * 8 + tg * 2;
            float bx = sbias[c], by = sbias[c + 1];
            if (g0 < N_SRC) {
                float2 v; v.x = acc[mt][nt][0] + bx; v.y = acc[mt][nt][1] + by;
                *(float2*)&g_WH[(size_t)g0 * D + c] = v;
            }
            if (g0 + 8 < N_SRC) {
                float2 v; v.x = acc[mt][nt][2] + bx; v.y = acc[mt][nt][3] + by;
                *(float2*)&g_WH[(size_t)(g0 + 8) * D + c] = v;
            }
        }
    }
}

// ---------------- degree counting ----------------
__global__ void count_kernel(const int* __restrict__ edge_dst) {
    int e = blockIdx.x * blockDim.x + threadIdx.x;
    if (e < E_CNT) atomicAdd(&g_deg[edge_dst[e]], 1);
}

// ---------------- 3-phase hierarchical scan ----------------
__global__ __launch_bounds__(SCAN_CHUNK) void scanA_kernel() {
    __shared__ int warp_sum[SCAN_CHUNK / 32];
    int idx = blockIdx.x * SCAN_CHUNK + threadIdx.x;
    int v = (idx < N_DST) ? g_deg[idx] : 0;
    for (int o = 16; o > 0; o >>= 1) v += __shfl_down_sync(0xffffffffu, v, o);
    int wid = threadIdx.x >> 5, lid = threadIdx.x & 31;
    if (lid == 0) warp_sum[wid] = v;
    __syncthreads();
    if (wid == 0) {
        int s = (lid < SCAN_CHUNK / 32) ? warp_sum[lid] : 0;
        for (int o = 16; o > 0; o >>= 1) s += __shfl_down_sync(0xffffffffu, s, o);
        if (lid == 0) g_part[blockIdx.x] = s;
    }
}
__global__ __launch_bounds__(128) void scanB_kernel() {
    __shared__ int sh[128];
    int tid = threadIdx.x;
    int v = (tid < SCAN_NB) ? g_part[tid] : 0;
    sh[tid] = v;
    __syncthreads();
    for (int o = 1; o < 128; o <<= 1) {
        int t = (tid >= o) ? sh[tid - o] : 0;
        __syncthreads();
        sh[tid] += t;
        __syncthreads();
    }
    if (tid < SCAN_NB) g_part[tid] = sh[tid] - v;
}
__global__ __launch_bounds__(SCAN_CHUNK) void scanC_kernel() {
    __shared__ int sh[SCAN_CHUNK];
    int tid = threadIdx.x;
    int idx = blockIdx.x * SCAN_CHUNK + tid;
    int v = (idx < N_DST) ? g_deg[idx] : 0;
    sh[tid] = v;
    __syncthreads();
    for (int o = 1; o < SCAN_CHUNK; o <<= 1) {
        int t = (tid >= o) ? sh[tid - o] : 0;
        __syncthreads();
        sh[tid] += t;
        __syncthreads();
    }
    int base = g_part[blockIdx.x];
    if (idx < N_DST) {
        g_off[idx] = base + sh[tid] - v;
        if (idx == N_DST - 1) g_off[N_DST] = base + sh[tid];
    }
}

// ---------------- CSR fill ----------------
__global__ void fill_kernel(const int* __restrict__ edge_src,
                            const int* __restrict__ edge_dst) {
    int e = blockIdx.x * blockDim.x + threadIdx.x;
    if (e < E_CNT) {
        int d = edge_dst[e];
        int pos = g_off[d] + atomicAdd(&g_cursor[d], 1);
        g_edges[pos] = edge_src[e];
    }
}

// ---------------- aggregation: one warp per dst, no atomics ----------------
__global__ __launch_bounds__(256) void agg_kernel(float* __restrict__ out) {
    int warp = (blockIdx.x * blockDim.x + threadIdx.x) >> 5;
    int lane = threadIdx.x & 31;
    if (warp >= N_DST) return;

    int s0 = g_off[warp];
    int s1 = g_off[warp + 1];

    const float4* WH4 = (const float4*)g_WH;
    float4 acc = make_float4(0.f, 0.f, 0.f, 0.f);

    int i = s0;
    for (; i + 3 < s1; i += 4) {
        int sA = g_edges[i];
        int sB = g_edges[i + 1];
        int sC = g_edges[i + 2];
        int sD = g_edges[i + 3];
        float4 a = WH4[(size_t)sA * 32 + lane];
        float4 c = WH4[(size_t)sB * 32 + lane];
        float4 e = WH4[(size_t)sC * 32 + lane];
        float4 f = WH4[(size_t)sD * 32 + lane];
        acc.x += (a.x + c.x) + (e.x + f.x);
        acc.y += (a.y + c.y) + (e.y + f.y);
        acc.z += (a.z + c.z) + (e.z + f.z);
        acc.w += (a.w + c.w) + (e.w + f.w);
    }
    for (; i < s1; i++) {
        int src = g_edges[i];
        float4 a = WH4[(size_t)src * 32 + lane];
        acc.x += a.x; acc.y += a.y; acc.z += a.z; acc.w += a.w;
    }

    float inv = 1.0f / fmaxf((float)(s1 - s0), 1.0f);
    acc.x = fmaxf(acc.x * inv, 0.f);
    acc.y = fmaxf(acc.y * inv, 0.f);
    acc.z = fmaxf(acc.z * inv, 0.f);
    acc.w = fmaxf(acc.w * inv, 0.f);

    ((float4*)out)[(size_t)warp * 32 + lane] = acc;
}

// ---------------- launch ----------------
extern "C" void kernel_launch(void* const* d_in, const int* in_sizes, int n_in,
                              void* d_out, int out_size) {
    const float* H_src    = (const float*)d_in[0];
    const float* W        = (const float*)d_in[1];
    const float* b        = (const float*)d_in[2];
    const int*   edge_src = (const int*)d_in[3];
    const int*   edge_dst = (const int*)d_in[4];
    float* out = (float*)d_out;

    static bool attr_set = false;
    if (!attr_set) {
        cudaFuncSetAttribute(gemm_tc_kernel,
                             cudaFuncAttributeMaxDynamicSharedMemorySize, SM_TOTAL);
        attr_set = true;
    }

    zero_counts_kernel<<<(N_DST + 255) / 256, 256>>>();
    wsplit_kernel<<<(D * D + 255) / 256, 256>>>(W);
    gemm_tc_kernel<<<GRID_M, 256, SM_TOTAL>>>(H_src, b);
    count_kernel<<<(E_CNT + 255) / 256, 256>>>(edge_dst);
    scanA_kernel<<<SCAN_NB, SCAN_CHUNK>>>();
    scanB_kernel<<<1, 128>>>();
    scanC_kernel<<<SCAN_NB, SCAN_CHUNK>>>();
    fill_kernel<<<(E_CNT + 255) / 256, 256>>>(edge_src, edge_dst);
    agg_kernel<<<(N_DST * 32 + 255) / 256, 256>>>(out);
}

// round 5
// speedup vs baseline: 2.3024x; 1.3147x over previous
#include <cuda_runtime.h>
#include <cuda_bf16.h>
#include <cstdint>

#define N_SRC  100000
#define N_DST  50000
#define E_CNT  600000
#define D      128          // D_IN == D_OUT == 128

#define SCAN_CHUNK 512
#define SCAN_NB    ((N_DST + SCAN_CHUNK - 1) / SCAN_CHUNK)   // 98

#define TILE_M 128
#define GRID_N ((N_DST + TILE_M - 1) / TILE_M)               // 391

// padded row stride for smem tiles (bf16 elements)
#define LDA 136

// ---------------- device scratch (no allocation allowed) ----------------
__device__ int   g_deg[N_DST];
__device__ int   g_cursor[N_DST];
__device__ int   g_off[N_DST + 1];
__device__ int   g_edges[E_CNT];
__device__ int   g_part[SCAN_NB];
__device__ float g_bflag[N_DST];                 // 1.0 if deg>0 else 0.0
// aggregated means, split bf16 hi/lo, row-major [N_DST][D]
__device__ __nv_bfloat16 g_Ahi[(size_t)N_DST * D];
__device__ __nv_bfloat16 g_Alo[(size_t)N_DST * D];
// W split into bf16 hi/lo, stored as B[n][k] (= W[k][n]) row-major, k contiguous
__device__ __nv_bfloat16 g_Whi[D * D];
__device__ __nv_bfloat16 g_Wlo[D * D];

// ---------------- helpers ----------------
__device__ __forceinline__ uint32_t smem_u32(const void* p) {
    uint32_t a;
    asm("{ .reg .u64 t; cvta.to.shared.u64 t, %1; cvt.u32.u64 %0, t; }" : "=r"(a) : "l"(p));
    return a;
}
__device__ __forceinline__ void mma16816(float* c,
                                         uint32_t a0, uint32_t a1, uint32_t a2, uint32_t a3,
                                         uint32_t b0, uint32_t b1) {
    asm volatile(
        "mma.sync.aligned.m16n8k16.row.col.f32.bf16.bf16.f32 "
        "{%0,%1,%2,%3}, {%4,%5,%6,%7}, {%8,%9}, {%0,%1,%2,%3};"
        : "+f"(c[0]), "+f"(c[1]), "+f"(c[2]), "+f"(c[3])
        : "r"(a0), "r"(a1), "r"(a2), "r"(a3), "r"(b0), "r"(b1));
}
__device__ __forceinline__ void ldsm_x4(uint32_t& r0, uint32_t& r1, uint32_t& r2, uint32_t& r3,
                                        uint32_t addr) {
    asm volatile("ldmatrix.sync.aligned.m8n8.x4.shared.b16 {%0,%1,%2,%3}, [%4];"
                 : "=r"(r0), "=r"(r1), "=r"(r2), "=r"(r3) : "r"(addr));
}
__device__ __forceinline__ uint32_t pack2(float a, float b) {
    __nv_bfloat162 t = __floats2bfloat162_rn(a, b);
    return *(uint32_t*)&t;
}

// ---------------- init: zero counters ----------------
__global__ void zero_counts_kernel() {
    int i = blockIdx.x * blockDim.x + threadIdx.x;
    if (i < N_DST) { g_deg[i] = 0; g_cursor[i] = 0; }
}

// ---------------- W split: B[n][k] = W[k][n], bf16 hi/lo ----------------
__global__ __launch_bounds__(256) void wsplit_kernel(const float* __restrict__ W) {
    int e = blockIdx.x * blockDim.x + threadIdx.x;
    if (e >= D * D) return;
    int n = e >> 7, k = e & 127;
    float w = W[k * D + n];
    __nv_bfloat16 hi = __float2bfloat16_rn(w);
    g_Whi[n * D + k] = hi;
    g_Wlo[n * D + k] = __float2bfloat16_rn(w - __bfloat162float(hi));
}

// ---------------- degree counting (4 edges/thread) ----------------
__global__ void count_kernel(const int* __restrict__ edge_dst) {
    int t = blockIdx.x * blockDim.x + threadIdx.x;
    if (t < E_CNT / 4) {
        int4 d = ((const int4*)edge_dst)[t];
        atomicAdd(&g_deg[d.x], 1);
        atomicAdd(&g_deg[d.y], 1);
        atomicAdd(&g_deg[d.z], 1);
        atomicAdd(&g_deg[d.w], 1);
    }
}

// ---------------- 3-phase hierarchical scan ----------------
__global__ __launch_bounds__(SCAN_CHUNK) void scanA_kernel() {
    __shared__ int warp_sum[SCAN_CHUNK / 32];
    int idx = blockIdx.x * SCAN_CHUNK + threadIdx.x;
    int v = (idx < N_DST) ? g_deg[idx] : 0;
    for (int o = 16; o > 0; o >>= 1) v += __shfl_down_sync(0xffffffffu, v, o);
    int wid = threadIdx.x >> 5, lid = threadIdx.x & 31;
    if (lid == 0) warp_sum[wid] = v;
    __syncthreads();
    if (wid == 0) {
        int s = (lid < SCAN_CHUNK / 32) ? warp_sum[lid] : 0;
        for (int o = 16; o > 0; o >>= 1) s += __shfl_down_sync(0xffffffffu, s, o);
        if (lid == 0) g_part[blockIdx.x] = s;
    }
}
__global__ __launch_bounds__(128) void scanB_kernel() {
    __shared__ int sh[128];
    int tid = threadIdx.x;
    int v = (tid < SCAN_NB) ? g_part[tid] : 0;
    sh[tid] = v;
    __syncthreads();
    for (int o = 1; o < 128; o <<= 1) {
        int t = (tid >= o) ? sh[tid - o] : 0;
        __syncthreads();
        sh[tid] += t;
        __syncthreads();
    }
    if (tid < SCAN_NB) g_part[tid] = sh[tid] - v;
}
__global__ __launch_bounds__(SCAN_CHUNK) void scanC_kernel() {
    __shared__ int sh[SCAN_CHUNK];
    int tid = threadIdx.x;
    int idx = blockIdx.x * SCAN_CHUNK + tid;
    int v = (idx < N_DST) ? g_deg[idx] : 0;
    sh[tid] = v;
    __syncthreads();
    for (int o = 1; o < SCAN_CHUNK; o <<= 1) {
        int t = (tid >= o) ? sh[tid - o] : 0;
        __syncthreads();
        sh[tid] += t;
        __syncthreads();
    }
    int base = g_part[blockIdx.x];
    if (idx < N_DST) {
        g_off[idx] = base + sh[tid] - v;
        if (idx == N_DST - 1) g_off[N_DST] = base + sh[tid];
    }
}

// ---------------- CSR fill (4 edges/thread) ----------------
__global__ void fill_kernel(const int* __restrict__ edge_src,
                            const int* __restrict__ edge_dst) {
    int t = blockIdx.x * blockDim.x + threadIdx.x;
    if (t < E_CNT / 4) {
        int4 s = ((const int4*)edge_src)[t];
        int4 d = ((const int4*)edge_dst)[t];
        g_edges[g_off[d.x] + atomicAdd(&g_cursor[d.x], 1)] = s.x;
        g_edges[g_off[d.y] + atomicAdd(&g_cursor[d.y], 1)] = s.y;
        g_edges[g_off[d.z] + atomicAdd(&g_cursor[d.z], 1)] = s.z;
        g_edges[g_off[d.w] + atomicAdd(&g_cursor[d.w], 1)] = s.w;
    }
}

// ---------------- aggregation of H: one warp per dst, mean, bf16-split out ---
__global__ __launch_bounds__(256) void aggH_kernel(const float* __restrict__ H) {
    int warp = (blockIdx.x * blockDim.x + threadIdx.x) >> 5;
    int lane = threadIdx.x & 31;
    if (warp >= N_DST) return;

    int s0 = g_off[warp];
    int s1 = g_off[warp + 1];

    const float4* H4 = (const float4*)H;
    float4 acc = make_float4(0.f, 0.f, 0.f, 0.f);

    int i = s0;
    for (; i + 3 < s1; i += 4) {
        int sA = g_edges[i],     sB = g_edges[i + 1];
        int sC = g_edges[i + 2], sD = g_edges[i + 3];
        float4 a = H4[(size_t)sA * 32 + lane];
        float4 c = H4[(size_t)sB * 32 + lane];
        float4 e = H4[(size_t)sC * 32 + lane];
        float4 f = H4[(size_t)sD * 32 + lane];
        acc.x += (a.x + c.x) + (e.x + f.x);
        acc.y += (a.y + c.y) + (e.y + f.y);
        acc.z += (a.z + c.z) + (e.z + f.z);
        acc.w += (a.w + c.w) + (e.w + f.w);
    }
    for (; i < s1; i++) {
        int src = g_edges[i];
        float4 a = H4[(size_t)src * 32 + lane];
        acc.x += a.x; acc.y += a.y; acc.z += a.z; acc.w += a.w;
    }

    float inv = 1.0f / fmaxf((float)(s1 - s0), 1.0f);
    acc.x *= inv; acc.y *= inv; acc.z *= inv; acc.w *= inv;

    __nv_bfloat16 h0 = __float2bfloat16_rn(acc.x);
    __nv_bfloat16 h1 = __float2bfloat16_rn(acc.y);
    __nv_bfloat16 h2 = __float2bfloat16_rn(acc.z);
    __nv_bfloat16 h3 = __float2bfloat16_rn(acc.w);
    uint2 hv, lv;
    { __nv_bfloat162 t0; t0.x = h0; t0.y = h1; hv.x = *(uint32_t*)&t0;
      __nv_bfloat162 t1; t1.x = h2; t1.y = h3; hv.y = *(uint32_t*)&t1; }
    lv.x = pack2(acc.x - __bfloat162float(h0), acc.y - __bfloat162float(h1));
    lv.y = pack2(acc.z - __bfloat162float(h2), acc.w - __bfloat162float(h3));

    ((uint2*)g_Ahi)[(size_t)warp * 32 + lane] = hv;
    ((uint2*)g_Alo)[(size_t)warp * 32 + lane] = lv;
    if (lane == 0) g_bflag[warp] = (s1 > s0) ? 1.0f : 0.0f;
}

// ---------------- GEMM: out = relu(aggH @ W + flag*b), split-bf16 + ldmatrix --
#define SM_BIAS  0
#define SM_AHI   512
#define SM_ALO   (SM_AHI + TILE_M * LDA * 2)
#define SM_BHI   (SM_ALO + TILE_M * LDA * 2)
#define SM_BLO   (SM_BHI + TILE_M * LDA * 2)
#define SM_TOTAL (SM_BLO + TILE_M * LDA * 2)       // 512 + 4*34816 = 139776

__global__ __launch_bounds__(256, 1) void gemm_tc_kernel(const float* __restrict__ b,
                                                         float* __restrict__ out) {
    extern __shared__ char smem[];
    const int tid = threadIdx.x;
    const int wid = tid >> 5, lane = tid & 31;
    const int block_row = blockIdx.x * TILE_M;

    __nv_bfloat16* sAhi = (__nv_bfloat16*)(smem + SM_AHI);
    __nv_bfloat16* sAlo = (__nv_bfloat16*)(smem + SM_ALO);
    __nv_bfloat16* sBhi = (__nv_bfloat16*)(smem + SM_BHI);
    __nv_bfloat16* sBlo = (__nv_bfloat16*)(smem + SM_BLO);
    float* sbias = (float*)(smem + SM_BIAS);

    // ---- load B tiles (16B chunks, padded rows) ----
    for (int i = tid; i < D * 16; i += 256) {
        int n = i >> 4, q = i & 15;
        *(uint4*)&sBhi[n * LDA + q * 8] = *(const uint4*)&g_Whi[n * D + q * 8];
        *(uint4*)&sBlo[n * LDA + q * 8] = *(const uint4*)&g_Wlo[n * D + q * 8];
    }
    if (tid < D) sbias[tid] = b[tid];

    // ---- load A tiles (pre-split bf16) ----
    {
        const uint4 z = make_uint4(0u, 0u, 0u, 0u);
        for (int i = tid; i < TILE_M * 16; i += 256) {
            int r = i >> 4, q = i & 15;
            int grow = block_row + r;
            uint4 hv = z, lv = z;
            if (grow < N_DST) {
                hv = *(const uint4*)&g_Ahi[(size_t)grow * D + q * 8];
                lv = *(const uint4*)&g_Alo[(size_t)grow * D + q * 8];
            }
            *(uint4*)&sAhi[r * LDA + q * 8] = hv;
            *(uint4*)&sAlo[r * LDA + q * 8] = lv;
        }
    }
    __syncthreads();

    // ---- per-warp MMA: warp covers rows [32*wr, +32), cols [64*wc, +64) ----
    const int wr = wid & 3, wc = wid >> 2;
    const int m0 = wr * 32, n0 = wc * 64;
    const int gid = lane >> 3 ? 0 : 0;  (void)gid;
    const int rit = lane & 7;
    const int g   = lane >> 3;          // lane group 0..3 (ldmatrix tile index)
    const int og  = lane >> 2;          // output row-in-tile 0..7
    const int tg  = lane & 3;

    const uint32_t sb = smem_u32(smem);
    // ldmatrix lane offsets (bytes) within a tile image
    const uint32_t aoff = (uint32_t)((m0 + rit + ((g & 1) << 3)) * LDA + ((g >> 1) << 3)) * 2;
    uint32_t boff[4];
#pragma unroll
    for (int p = 0; p < 4; p++)
        boff[p] = (uint32_t)((n0 + p * 16 + rit + ((g >> 1) << 3)) * LDA + ((g & 1) << 3)) * 2;

    float acc[2][8][4];
#pragma unroll
    for (int mt = 0; mt < 2; mt++)
#pragma unroll
        for (int nt = 0; nt < 8; nt++)
#pragma unroll
            for (int q = 0; q < 4; q++) acc[mt][nt][q] = 0.f;

#pragma unroll
    for (int pass = 0; pass < 3; pass++) {
        const uint32_t aBase = sb + ((pass == 2) ? SM_ALO : SM_AHI) + aoff;
        const uint32_t bBase = sb + ((pass == 1) ? SM_BLO : SM_BHI);
#pragma unroll
        for (int ks = 0; ks < 8; ks++) {
            const uint32_t kb = ks * 32;     // 16 bf16 = 32 bytes
            uint32_t a0[4], a1[4];
            ldsm_x4(a0[0], a0[1], a0[2], a0[3], aBase + kb);
            ldsm_x4(a1[0], a1[1], a1[2], a1[3], aBase + 16 * LDA * 2 + kb);
#pragma unroll
            for (int p = 0; p < 4; p++) {
                uint32_t r0, r1, r2, r3;
                ldsm_x4(r0, r1, r2, r3, bBase + boff[p] + kb);
                mma16816(acc[0][2 * p    ], a0[0], a0[1], a0[2], a0[3], r0, r1);
                mma16816(acc[1][2 * p    ], a1[0], a1[1], a1[2], a1[3], r0, r1);
                mma16816(acc[0][2 * p + 1], a0[0], a0[1], a0[2], a0[3], r2, r3);
                mma16816(acc[1][2 * p + 1], a1[0], a1[1], a1[2], a1[3], r2, r3);
            }
        }
    }

    // ---- epilogue: bias*flag + relu, store to out ----
#pragma unroll
    for (int mt = 0; mt < 2; mt++) {
        const int r  = m0 + mt * 16 + og;
        const int gA = block_row + r;
        const int gB = gA + 8;
        float fA = (gA < N_DST) ? g_bflag[gA] : 0.f;
        float fB = (gB < N_DST) ? g_bflag[gB] : 0.f;
#pragma unroll
        for (int nt = 0; nt < 8; nt++) {
            const int c = n0 + nt * 8 + tg * 2;
            float bx = sbias[c], by = sbias[c + 1];
            if (gA < N_DST) {
                float2 v;
                v.x = fmaxf(acc[mt][nt][0] + bx * fA, 0.f);
                v.y = fmaxf(acc[mt][nt][1] + by * fA, 0.f);
                *(float2*)&out[(size_t)gA * D + c] = v;
            }
            if (gB < N_DST) {
                float2 v;
                v.x = fmaxf(acc[mt][nt][2] + bx * fB, 0.f);
                v.y = fmaxf(acc[mt][nt][3] + by * fB, 0.f);
                *(float2*)&out[(size_t)gB * D + c] = v;
            }
        }
    }
}

// ---------------- launch ----------------
extern "C" void kernel_launch(void* const* d_in, const int* in_sizes, int n_in,
                              void* d_out, int out_size) {
    const float* H_src    = (const float*)d_in[0];
    const float* W        = (const float*)d_in[1];
    const float* b        = (const float*)d_in[2];
    const int*   edge_src = (const int*)d_in[3];
    const int*   edge_dst = (const int*)d_in[4];
    float* out = (float*)d_out;

    static bool attr_set = false;
    if (!attr_set) {
        cudaFuncSetAttribute(gemm_tc_kernel,
                             cudaFuncAttributeMaxDynamicSharedMemorySize, SM_TOTAL);
        attr_set = true;
    }

    zero_counts_kernel<<<(N_DST + 255) / 256, 256>>>();
    wsplit_kernel<<<(D * D + 255) / 256, 256>>>(W);
    count_kernel<<<(E_CNT / 4 + 255) / 256, 256>>>(edge_dst);
    scanA_kernel<<<SCAN_NB, SCAN_CHUNK>>>();
    scanB_kernel<<<1, 128>>>();
    scanC_kernel<<<SCAN_NB, SCAN_CHUNK>>>();
    fill_kernel<<<(E_CNT / 4 + 255) / 256, 256>>>(edge_src, edge_dst);
    aggH_kernel<<<(N_DST * 32 + 255) / 256, 256>>>(H_src);
    gemm_tc_kernel<<<GRID_N, 256, SM_TOTAL>>>(b, out);
}